// round 8
// baseline (speedup 1.0000x reference)
#include <cuda_runtime.h>
#include <cstdint>
#include <float.h>

#define BB 4
#define NN 40960
#define KK 16
#define DD 64
#define HH 32
#define NPTS (BB * NN)
#define EPSV 1e-5f

typedef unsigned long long ull;
typedef unsigned int u32;

// ---------- packed f32x2 helpers ----------
__device__ __forceinline__ ull ffma2(ull a, ull b, ull c) {
    ull d;
    asm("fma.rn.f32x2 %0, %1, %2, %3;" : "=l"(d) : "l"(a), "l"(b), "l"(c));
    return d;
}
__device__ __forceinline__ ull pack2(float lo, float hi) {
    ull d;
    asm("mov.b64 %0, {%1, %2};" : "=l"(d) : "f"(lo), "f"(hi));
    return d;
}
__device__ __forceinline__ void unpack2(ull v, float& lo, float& hi) {
    asm("mov.b64 {%0, %1}, %2;" : "=f"(lo), "=f"(hi) : "l"(v));
}
__device__ __forceinline__ u32 smem_u32(const void* p) {
    return (u32)__cvta_generic_to_shared(p);
}

// ---------- folded weights ----------
__device__ ull dW2P[DD][HH / 2];        // [c][hp]
__device__ ull dW3AP[HH][HH / 2];       // W3[:, 0:32]  (applies to gathered f)
__device__ ulonglong2 dW3B2[HH][8];     // W3[:, 32:64] as ulonglong2 pairs
__device__ ull dW4P[2 * HH][DD / 2];    // [c][dp]
// packed-over-output-channel-pair coefficients for fx:
__device__ ulonglong2 dMA[16];          // (m1x2, m1y2) per cp  (neighbor xyz terms)
__device__ ulonglong2 dMB[16];          // (m1z2, w1d2) per cp  (neighbor z + distance)
__device__ ull dM0X2[16], dM0Y2[16], dM0Z2[16], dB12[16];  // center terms + b1
__device__ float dB2[HH], dB3[HH], dB4[DD];
__device__ int dIdx64;

// ---------- scratch ----------
__device__ float dF[NPTS * HH];     // f per point (post-ReLU)
__device__ float dG[NPTS * HH];     // G = s3*(W3a@f)+b3, packed output-pair layout (128B row)
__device__ float dFC[NPTS * HH];    // max-pooled f_concat (post-ReLU)
__device__ float4 dXYZ4[NPTS];      // (x, y, z, 0)

// ================== prep ==================
__global__ void prep_kernel(const float* __restrict__ W1, const float* __restrict__ W2,
                            const float* __restrict__ W3, const float* __restrict__ W4,
                            const float* __restrict__ g1, const float* __restrict__ b1,
                            const float* __restrict__ g2, const float* __restrict__ b2,
                            const float* __restrict__ g3, const float* __restrict__ b3,
                            const float* __restrict__ g4, const float* __restrict__ b4) {
    int t = threadIdx.x;
    float inv = rsqrtf(1.0f + EPSV);
    for (int i = t; i < DD * (HH / 2); i += blockDim.x) {
        int c = i >> 4, hp = i & 15;
        dW2P[c][hp] = pack2(g2[2 * hp] * inv * W2[(2 * hp) * DD + c],
                            g2[2 * hp + 1] * inv * W2[(2 * hp + 1) * DD + c]);
    }
    for (int i = t; i < HH * (HH / 2); i += blockDim.x) {
        int c = i >> 4, hp = i & 15;
        float s0 = g3[2 * hp] * inv, s1 = g3[2 * hp + 1] * inv;
        dW3AP[c][hp] = pack2(s0 * W3[(2 * hp) * (2 * HH) + c],
                             s1 * W3[(2 * hp + 1) * (2 * HH) + c]);
    }
    for (int i = t; i < HH * 8; i += blockDim.x) {
        int c = i >> 3, hq = i & 7;
        float sA = g3[4 * hq] * inv, sB = g3[4 * hq + 1] * inv;
        float sC = g3[4 * hq + 2] * inv, sD = g3[4 * hq + 3] * inv;
        dW3B2[c][hq] = make_ulonglong2(
            pack2(sA * W3[(4 * hq) * (2 * HH) + HH + c], sB * W3[(4 * hq + 1) * (2 * HH) + HH + c]),
            pack2(sC * W3[(4 * hq + 2) * (2 * HH) + HH + c], sD * W3[(4 * hq + 3) * (2 * HH) + HH + c]));
    }
    for (int i = t; i < (2 * HH) * (DD / 2); i += blockDim.x) {
        int c = i >> 5, dp = i & 31;
        dW4P[c][dp] = pack2(g4[2 * dp] * inv * W4[(2 * dp) * (2 * HH) + c],
                            g4[2 * dp + 1] * inv * W4[(2 * dp + 1) * (2 * HH) + c]);
    }
    for (int cp = t; cp < 16; cp += blockDim.x) {
        int h0 = 2 * cp, h1 = 2 * cp + 1;
        float s0 = g1[h0] * inv, s1 = g1[h1] * inv;
        float m1x0 = s0 * (W1[h0 * 10 + 7] - W1[h0 * 10 + 1]), m1x1 = s1 * (W1[h1 * 10 + 7] - W1[h1 * 10 + 1]);
        float m1y0 = s0 * (W1[h0 * 10 + 8] - W1[h0 * 10 + 2]), m1y1 = s1 * (W1[h1 * 10 + 8] - W1[h1 * 10 + 2]);
        float m1z0 = s0 * (W1[h0 * 10 + 9] - W1[h0 * 10 + 3]), m1z1 = s1 * (W1[h1 * 10 + 9] - W1[h1 * 10 + 3]);
        float wd0 = s0 * W1[h0 * 10 + 0], wd1 = s1 * W1[h1 * 10 + 0];
        dMA[cp] = make_ulonglong2(pack2(m1x0, m1x1), pack2(m1y0, m1y1));
        dMB[cp] = make_ulonglong2(pack2(m1z0, m1z1), pack2(wd0, wd1));
        dM0X2[cp] = pack2(s0 * (W1[h0 * 10 + 1] + W1[h0 * 10 + 4]), s1 * (W1[h1 * 10 + 1] + W1[h1 * 10 + 4]));
        dM0Y2[cp] = pack2(s0 * (W1[h0 * 10 + 2] + W1[h0 * 10 + 5]), s1 * (W1[h1 * 10 + 2] + W1[h1 * 10 + 5]));
        dM0Z2[cp] = pack2(s0 * (W1[h0 * 10 + 3] + W1[h0 * 10 + 6]), s1 * (W1[h1 * 10 + 3] + W1[h1 * 10 + 6]));
        dB12[cp] = pack2(b1[h0], b1[h1]);
    }
    for (int h = t; h < HH; h += blockDim.x) { dB2[h] = b2[h]; dB3[h] = b3[h]; }
    for (int d = t; d < DD; d += blockDim.x) dB4[d] = b4[d];
}

// ================== detect int64 vs int32 neigh_idx ==================
__global__ void detect_kernel(const unsigned int* __restrict__ w) {
    __shared__ int sBad;
    if (threadIdx.x == 0) sBad = 0;
    __syncthreads();
    unsigned int acc = 0;
    for (int i = threadIdx.x; i < 2048; i += blockDim.x) acc |= w[2 * i + 1];
    if (acc) atomicOr(&sBad, 1);
    __syncthreads();
    if (threadIdx.x == 0) dIdx64 = (sBad == 0) ? 1 : 0;
}

// ================== pass 1: per-point f, G = W3a@f+b3, xyz4 ==================
__global__ void __launch_bounds__(128) pass1_kernel(const float* __restrict__ feat,
                                                    const float* __restrict__ xyz) {
    __shared__ ull sW2[DD][HH / 2];
    __shared__ ull sW3A[HH][HH / 2];
    __shared__ float sB2[HH], sB3[HH];
    int tid = threadIdx.x;
    for (int i = tid; i < DD * (HH / 2); i += 128) ((ull*)sW2)[i] = ((ull*)dW2P)[i];
    for (int i = tid; i < HH * (HH / 2); i += 128) ((ull*)sW3A)[i] = ((ull*)dW3AP)[i];
    if (tid < HH) { sB2[tid] = dB2[tid]; sB3[tid] = dB3[tid]; }
    __syncthreads();

    int p = blockIdx.x * 128 + tid;
    int b = p / NN;
    int n = p - b * NN;

    ull acc[HH / 2];
#pragma unroll
    for (int hp = 0; hp < 16; hp++) acc[hp] = 0ull;
    const float* fp = feat + (size_t)b * DD * NN + n;
#pragma unroll
    for (int c = 0; c < DD; c++) {
        float x = fp[(size_t)c * NN];
        ull xd = pack2(x, x);
#pragma unroll
        for (int hp = 0; hp < 16; hp++) acc[hp] = ffma2(sW2[c][hp], xd, acc[hp]);
    }
    float f[HH];
#pragma unroll
    for (int hp = 0; hp < 16; hp++) {
        float lo, hi;
        unpack2(acc[hp], lo, hi);
        f[2 * hp] = fmaxf(lo + sB2[2 * hp], 0.0f);
        f[2 * hp + 1] = fmaxf(hi + sB2[2 * hp + 1], 0.0f);
    }
    float* Frow = dF + (size_t)p * HH;
#pragma unroll
    for (int q = 0; q < 8; q++)
        ((float4*)Frow)[q] = make_float4(f[4 * q], f[4 * q + 1], f[4 * q + 2], f[4 * q + 3]);

    // G = s3*(W3a @ f) + b3 (packed output-pair layout)
#pragma unroll
    for (int hp = 0; hp < 16; hp++) acc[hp] = pack2(sB3[2 * hp], sB3[2 * hp + 1]);
#pragma unroll
    for (int c = 0; c < HH; c++) {
        ull xd = pack2(f[c], f[c]);
#pragma unroll
        for (int hp = 0; hp < 16; hp++) acc[hp] = ffma2(sW3A[c][hp], xd, acc[hp]);
    }
    ull* Grow = (ull*)(dG + (size_t)p * HH);
#pragma unroll
    for (int hp = 0; hp < 16; hp++) Grow[hp] = acc[hp];

    const float* xp = xyz + (size_t)p * 3;
    dXYZ4[p] = make_float4(xp[0], xp[1], xp[2], 0.0f);
}

// ================== pass 2: pipelined gather + packed matvec + max-pool ==================
#define RSTRIDE 36  // floats per staged row (32 + 4 pad)

__global__ void __launch_bounds__(128, 4) pass2_kernel(const unsigned int* __restrict__ idxw) {
    __shared__ ulonglong2 sW3B2[HH][8];              // 4 KB
    __shared__ ulonglong2 sMA[16], sMB[16];          // 512 B
    __shared__ float sStage[2][4][32 * RSTRIDE];     // 36864 B double-buffered G stage
    __shared__ int sIdx[128 * 17];                   // 8704 B
    int tid = threadIdx.x;
    for (int i = tid; i < HH * 8; i += 128) {
        int c = i >> 3, hq = i & 7;
        sW3B2[c][hq] = dW3B2[c][hq];
    }
    if (tid < 16) { sMA[tid] = dMA[tid]; sMB[tid] = dMB[tid]; }
    int shift = dIdx64;
    {
        unsigned int gbase = (unsigned int)blockIdx.x * 2048u;
        for (int i = tid; i < 2048; i += 128) {
            unsigned int w = idxw[(size_t)(gbase + i) << shift];
            sIdx[(i >> 4) * 17 + (i & 15)] = (int)w;
        }
    }
    __syncthreads();

    int p = blockIdx.x * 128 + tid;
    int b = p / NN;
    int lane = tid & 31;
    int warp = tid >> 5;
    int bBase = b * NN;

    // per-point base (packed): bp = B12 + M0X2*x0 + M0Y2*y0 + M0Z2*z0
    float4 xc = dXYZ4[p];
    ull x02 = pack2(xc.x, xc.x), y02 = pack2(xc.y, xc.y), z02 = pack2(xc.z, xc.z);
    ull bp[16];
#pragma unroll
    for (int cp = 0; cp < 16; cp++)
        bp[cp] = ffma2(dM0X2[cp], x02, ffma2(dM0Y2[cp], y02, ffma2(dM0Z2[cp], z02, dB12[cp])));

    float fc[HH];
#pragma unroll
    for (int h = 0; h < HH; h++) fc[h] = -FLT_MAX;

    int srcrow = lane >> 3;     // this lane's row-within-group (0..3)
    int col = lane & 7;         // this lane's float4 column (0..7)
    u32 stbase[2];
    stbase[0] = smem_u32(&sStage[0][warp][0]) + (u32)((srcrow * RSTRIDE + col * 4) * 4);
    stbase[1] = smem_u32(&sStage[1][warp][0]) + (u32)((srcrow * RSTRIDE + col * 4) * 4);

    // ---- prologue: prefetch k=0 ----
    int rjn = bBase + sIdx[tid * 17 + 0];
#pragma unroll
    for (int i = 0; i < 8; i++) {
        int rs = __shfl_sync(0xffffffffu, rjn, 4 * i + srcrow);
        const float* g = dG + (size_t)rs * HH + col * 4;
        asm volatile("cp.async.cg.shared.global [%0], [%1], 16;"
                     :: "r"(stbase[0] + (u32)(4 * i * RSTRIDE * 4)), "l"(g));
    }
    asm volatile("cp.async.commit_group;");
    float4 xyzn = dXYZ4[rjn];

#pragma unroll 1
    for (int k = 0; k < KK; k++) {
        int cur = k & 1, nxt = cur ^ 1;
        float4 xyzj = xyzn;
        __syncwarp();  // previous readers of buf[nxt] are done
        // prefetch k+1
        int kn = (k < KK - 1) ? k + 1 : KK - 1;
        rjn = bBase + sIdx[tid * 17 + kn];
#pragma unroll
        for (int i = 0; i < 8; i++) {
            int rs = __shfl_sync(0xffffffffu, rjn, 4 * i + srcrow);
            const float* g = dG + (size_t)rs * HH + col * 4;
            asm volatile("cp.async.cg.shared.global [%0], [%1], 16;"
                         :: "r"(stbase[nxt] + (u32)(4 * i * RSTRIDE * 4)), "l"(g));
        }
        asm volatile("cp.async.commit_group;");
        xyzn = dXYZ4[rjn];
        asm volatile("cp.async.wait_group 1;");
        __syncwarp();  // k's staged data visible warp-wide

        // --- distance + splats ---
        float dx = xc.x - xyzj.x, dy = xc.y - xyzj.y, dz = xc.z - xyzj.z;
        float dis = sqrtf(dx * dx + dy * dy + dz * dz);
        ull xj2 = pack2(xyzj.x, xyzj.x), yj2 = pack2(xyzj.y, xyzj.y);
        ull zj2 = pack2(xyzj.z, xyzj.z), dis2 = pack2(dis, dis);

        // --- acc init = staged G (this lane's own row) ---
        ull acc[16];
        const ulonglong2* gsrc = (const ulonglong2*)&sStage[cur][warp][lane * RSTRIDE];
#pragma unroll
        for (int q = 0; q < 8; q++) {
            ulonglong2 v = gsrc[q];
            acc[2 * q] = v.x;
            acc[2 * q + 1] = v.y;
        }

        // --- packed fx + W3b matvec ---
#pragma unroll
        for (int cp = 0; cp < 16; cp++) {
            ulonglong2 wa = sMA[cp], wb = sMB[cp];
            ull t2 = ffma2(wa.x, xj2, bp[cp]);
            t2 = ffma2(wa.y, yj2, t2);
            t2 = ffma2(wb.x, zj2, t2);
            t2 = ffma2(wb.y, dis2, t2);
            float f0, f1;
            unpack2(t2, f0, f1);
            f0 = fmaxf(f0, 0.0f);
            f1 = fmaxf(f1, 0.0f);
            ull s0 = pack2(f0, f0), s1 = pack2(f1, f1);
            int c0 = 2 * cp, c1 = c0 + 1;
#pragma unroll
            for (int hq = 0; hq < 8; hq++) {
                ulonglong2 w0 = sW3B2[c0][hq];
                acc[2 * hq] = ffma2(w0.x, s0, acc[2 * hq]);
                acc[2 * hq + 1] = ffma2(w0.y, s0, acc[2 * hq + 1]);
            }
#pragma unroll
            for (int hq = 0; hq < 8; hq++) {
                ulonglong2 w1 = sW3B2[c1][hq];
                acc[2 * hq] = ffma2(w1.x, s1, acc[2 * hq]);
                acc[2 * hq + 1] = ffma2(w1.y, s1, acc[2 * hq + 1]);
            }
        }

        // --- max pool ---
#pragma unroll
        for (int hp = 0; hp < 16; hp++) {
            float lo, hi;
            unpack2(acc[hp], lo, hi);
            fc[2 * hp] = fmaxf(fc[2 * hp], lo);
            fc[2 * hp + 1] = fmaxf(fc[2 * hp + 1], hi);
        }
    }

    float* op = dFC + (size_t)p * HH;
#pragma unroll
    for (int q = 0; q < 8; q++)
        ((float4*)op)[q] = make_float4(fmaxf(fc[4 * q], 0.0f), fmaxf(fc[4 * q + 1], 0.0f),
                                       fmaxf(fc[4 * q + 2], 0.0f), fmaxf(fc[4 * q + 3], 0.0f));
}

// ================== pass 3: out = relu(W4' @ [fc; f] + b4) ==================
__global__ void __launch_bounds__(64) pass3_kernel(float* __restrict__ out) {
    __shared__ ull sW4[2 * HH][DD / 2];  // 16 KB
    __shared__ float sB4[DD];
    __shared__ float sFC[64 * 33];
    __shared__ float sF[64 * 33];
    int tid = threadIdx.x;
    for (int i = tid; i < 2 * HH * (DD / 2); i += 64) ((ull*)sW4)[i] = ((ull*)dW4P)[i];
    if (tid < DD) sB4[tid] = dB4[tid];
    int pbase = blockIdx.x * 64;
    for (int i = tid; i < 64 * HH; i += 64) {
        int r = i >> 5, c = i & 31;
        sFC[r * 33 + c] = dFC[(size_t)pbase * HH + i];
        sF[r * 33 + c] = dF[(size_t)pbase * HH + i];
    }
    __syncthreads();

    int p = pbase + tid;
    int b = p / NN;
    int n = p - b * NN;

    ull acc[DD / 2];
#pragma unroll
    for (int dp = 0; dp < 32; dp++) acc[dp] = pack2(sB4[2 * dp], sB4[2 * dp + 1]);
#pragma unroll
    for (int c = 0; c < HH; c++) {
        float v = sFC[tid * 33 + c];
        ull x2 = pack2(v, v);
        const ulonglong2* wr = (const ulonglong2*)sW4[c];
#pragma unroll
        for (int dq = 0; dq < 16; dq++) {
            ulonglong2 w = wr[dq];
            acc[2 * dq] = ffma2(w.x, x2, acc[2 * dq]);
            acc[2 * dq + 1] = ffma2(w.y, x2, acc[2 * dq + 1]);
        }
    }
#pragma unroll
    for (int c = 0; c < HH; c++) {
        float v = sF[tid * 33 + c];
        ull x2 = pack2(v, v);
        const ulonglong2* wr = (const ulonglong2*)sW4[HH + c];
#pragma unroll
        for (int dq = 0; dq < 16; dq++) {
            ulonglong2 w = wr[dq];
            acc[2 * dq] = ffma2(w.x, x2, acc[2 * dq]);
            acc[2 * dq + 1] = ffma2(w.y, x2, acc[2 * dq + 1]);
        }
    }
    float* op = out + (size_t)b * DD * NN + n;
#pragma unroll
    for (int dp = 0; dp < 32; dp++) {
        float lo, hi;
        unpack2(acc[dp], lo, hi);
        op[(size_t)(2 * dp) * NN] = fmaxf(lo, 0.0f);
        op[(size_t)(2 * dp + 1) * NN] = fmaxf(hi, 0.0f);
    }
}

// ================== launch ==================
extern "C" void kernel_launch(void* const* d_in, const int* in_sizes, int n_in,
                              void* d_out, int out_size) {
    const float *feat, *xyz, *W1, *W2, *W3, *W4;
    const float *g1, *b1, *g2, *b2, *g3, *b3, *g4, *b4;
    const void* idx;
    if (n_in >= 3 && in_sizes[2] == 320) {
        feat = (const float*)d_in[0];  xyz = (const float*)d_in[1];
        W1 = (const float*)d_in[2];    g1 = (const float*)d_in[3];  b1 = (const float*)d_in[4];
        W2 = (const float*)d_in[5];    g2 = (const float*)d_in[6];  b2 = (const float*)d_in[7];
        W3 = (const float*)d_in[8];    g3 = (const float*)d_in[9];  b3 = (const float*)d_in[10];
        W4 = (const float*)d_in[11];   g4 = (const float*)d_in[12]; b4 = (const float*)d_in[13];
        idx = d_in[14];
    } else {
        feat = (const float*)d_in[0];  xyz = (const float*)d_in[1];  idx = d_in[2];
        W1 = (const float*)d_in[3];    W2 = (const float*)d_in[4];
        W3 = (const float*)d_in[5];    W4 = (const float*)d_in[6];
        g1 = (const float*)d_in[7];    b1 = (const float*)d_in[8];
        g2 = (const float*)d_in[9];    b2 = (const float*)d_in[10];
        g3 = (const float*)d_in[11];   b3 = (const float*)d_in[12];
        g4 = (const float*)d_in[13];   b4 = (const float*)d_in[14];
    }
    prep_kernel<<<1, 256>>>(W1, W2, W3, W4, g1, b1, g2, b2, g3, b3, g4, b4);
    detect_kernel<<<1, 256>>>((const unsigned int*)idx);
    pass1_kernel<<<NPTS / 128, 128>>>(feat, xyz);
    pass2_kernel<<<NPTS / 128, 128>>>((const unsigned int*)idx);
    pass3_kernel<<<NPTS / 64, 64>>>((float*)d_out);
}

// round 9
// speedup vs baseline: 1.6385x; 1.6385x over previous
#include <cuda_runtime.h>
#include <cstdint>
#include <float.h>

#define BB 4
#define NN 40960
#define KK 16
#define DD 64
#define HH 32
#define NPTS (BB * NN)
#define EPSV 1e-5f
#define PPW 16   // points per warp in pass2

typedef unsigned long long ull;
typedef unsigned int u32;

// ---------- packed f32x2 helpers ----------
__device__ __forceinline__ ull ffma2(ull a, ull b, ull c) {
    ull d;
    asm("fma.rn.f32x2 %0, %1, %2, %3;" : "=l"(d) : "l"(a), "l"(b), "l"(c));
    return d;
}
__device__ __forceinline__ ull pack2(float lo, float hi) {
    ull d;
    asm("mov.b64 %0, {%1, %2};" : "=l"(d) : "f"(lo), "f"(hi));
    return d;
}
__device__ __forceinline__ void unpack2(ull v, float& lo, float& hi) {
    asm("mov.b64 {%0, %1}, %2;" : "=f"(lo), "=f"(hi) : "l"(v));
}
__device__ __forceinline__ u32 cvt_tf32(float f) {
    u32 r;
    asm("cvt.rna.tf32.f32 %0, %1;" : "=r"(r) : "f"(f));
    return r;
}
__device__ __forceinline__ void mma_tf32(float& c0, float& c1, float& c2, float& c3,
                                         u32 a0, u32 a1, u32 a2, u32 a3, u32 b0, u32 b1) {
    asm("mma.sync.aligned.m16n8k8.row.col.f32.tf32.tf32.f32 "
        "{%0,%1,%2,%3}, {%4,%5,%6,%7}, {%8,%9}, {%0,%1,%2,%3};"
        : "+f"(c0), "+f"(c1), "+f"(c2), "+f"(c3)
        : "r"(a0), "r"(a1), "r"(a2), "r"(a3), "r"(b0), "r"(b1));
}

// ---------- folded weights ----------
__device__ ull dW2P[DD][HH / 2];        // [c][hp]  (pass1)
__device__ ull dW3AP[HH][HH / 2];       // W3[:, 0:32] (pass1)
__device__ u32 dW3Btf[HH * HH];         // [h][c] = tf32(s3*W3[h][32+c])  (pass2 B frags)
__device__ ull dW4P[2 * HH][DD / 2];    // [c][dp] (pass3)
__device__ float4 dCoefA[HH];           // (m1x, m1y, m1z, w1d) per channel
__device__ float4 dCoefB[HH];           // (m0x, m0y, m0z, b1)  per channel
__device__ float dB2[HH], dB3[HH], dB4[DD];
__device__ int dIdx64;

// ---------- scratch ----------
__device__ float dF[NPTS * HH];     // f per point (post-ReLU)
__device__ float dG[NPTS * HH];     // G = s3*(W3a@f)+b3, PERMUTED: float off = tig*8 + nt*2 + e
__device__ float dFC[NPTS * HH];    // max-pooled f_concat (post-ReLU), plain order
__device__ float4 dXYZ4[NPTS];      // (x, y, z, 0)

// ================== prep ==================
__global__ void prep_kernel(const float* __restrict__ W1, const float* __restrict__ W2,
                            const float* __restrict__ W3, const float* __restrict__ W4,
                            const float* __restrict__ g1, const float* __restrict__ b1,
                            const float* __restrict__ g2, const float* __restrict__ b2,
                            const float* __restrict__ g3, const float* __restrict__ b3,
                            const float* __restrict__ g4, const float* __restrict__ b4) {
    int t = threadIdx.x;
    float inv = rsqrtf(1.0f + EPSV);
    for (int i = t; i < DD * (HH / 2); i += blockDim.x) {
        int c = i >> 4, hp = i & 15;
        dW2P[c][hp] = pack2(g2[2 * hp] * inv * W2[(2 * hp) * DD + c],
                            g2[2 * hp + 1] * inv * W2[(2 * hp + 1) * DD + c]);
    }
    for (int i = t; i < HH * (HH / 2); i += blockDim.x) {
        int c = i >> 4, hp = i & 15;
        float s0 = g3[2 * hp] * inv, s1 = g3[2 * hp + 1] * inv;
        dW3AP[c][hp] = pack2(s0 * W3[(2 * hp) * (2 * HH) + c],
                             s1 * W3[(2 * hp + 1) * (2 * HH) + c]);
    }
    for (int i = t; i < HH * HH; i += blockDim.x) {
        int h = i >> 5, c = i & 31;
        dW3Btf[h * HH + c] = cvt_tf32(g3[h] * inv * W3[h * (2 * HH) + HH + c]);
    }
    for (int i = t; i < (2 * HH) * (DD / 2); i += blockDim.x) {
        int c = i >> 5, dp = i & 31;
        dW4P[c][dp] = pack2(g4[2 * dp] * inv * W4[(2 * dp) * (2 * HH) + c],
                            g4[2 * dp + 1] * inv * W4[(2 * dp + 1) * (2 * HH) + c]);
    }
    for (int c = t; c < HH; c += blockDim.x) {
        float s = g1[c] * inv;
        dCoefA[c] = make_float4(s * (W1[c * 10 + 7] - W1[c * 10 + 1]),
                                s * (W1[c * 10 + 8] - W1[c * 10 + 2]),
                                s * (W1[c * 10 + 9] - W1[c * 10 + 3]),
                                s * W1[c * 10 + 0]);
        dCoefB[c] = make_float4(s * (W1[c * 10 + 1] + W1[c * 10 + 4]),
                                s * (W1[c * 10 + 2] + W1[c * 10 + 5]),
                                s * (W1[c * 10 + 3] + W1[c * 10 + 6]),
                                b1[c]);
        dB2[c] = b2[c];
        dB3[c] = b3[c];
    }
    for (int d = t; d < DD; d += blockDim.x) dB4[d] = b4[d];
}

// ================== detect int64 vs int32 neigh_idx ==================
__global__ void detect_kernel(const unsigned int* __restrict__ w) {
    __shared__ int sBad;
    if (threadIdx.x == 0) sBad = 0;
    __syncthreads();
    unsigned int acc = 0;
    for (int i = threadIdx.x; i < 2048; i += blockDim.x) acc |= w[2 * i + 1];
    if (acc) atomicOr(&sBad, 1);
    __syncthreads();
    if (threadIdx.x == 0) dIdx64 = (sBad == 0) ? 1 : 0;
}

// ================== pass 1: per-point f, G (permuted), xyz4 ==================
__global__ void __launch_bounds__(128) pass1_kernel(const float* __restrict__ feat,
                                                    const float* __restrict__ xyz) {
    __shared__ ull sW2[DD][HH / 2];
    __shared__ ull sW3A[HH][HH / 2];
    __shared__ float sB2[HH], sB3[HH];
    int tid = threadIdx.x;
    for (int i = tid; i < DD * (HH / 2); i += 128) ((ull*)sW2)[i] = ((ull*)dW2P)[i];
    for (int i = tid; i < HH * (HH / 2); i += 128) ((ull*)sW3A)[i] = ((ull*)dW3AP)[i];
    if (tid < HH) { sB2[tid] = dB2[tid]; sB3[tid] = dB3[tid]; }
    __syncthreads();

    int p = blockIdx.x * 128 + tid;
    int b = p / NN;
    int n = p - b * NN;

    ull acc[HH / 2];
#pragma unroll
    for (int hp = 0; hp < 16; hp++) acc[hp] = 0ull;
    const float* fp = feat + (size_t)b * DD * NN + n;
#pragma unroll
    for (int c = 0; c < DD; c++) {
        float x = fp[(size_t)c * NN];
        ull xd = pack2(x, x);
#pragma unroll
        for (int hp = 0; hp < 16; hp++) acc[hp] = ffma2(sW2[c][hp], xd, acc[hp]);
    }
    float f[HH];
#pragma unroll
    for (int hp = 0; hp < 16; hp++) {
        float lo, hi;
        unpack2(acc[hp], lo, hi);
        f[2 * hp] = fmaxf(lo + sB2[2 * hp], 0.0f);
        f[2 * hp + 1] = fmaxf(hi + sB2[2 * hp + 1], 0.0f);
    }
    float* Frow = dF + (size_t)p * HH;
#pragma unroll
    for (int q = 0; q < 8; q++)
        ((float4*)Frow)[q] = make_float4(f[4 * q], f[4 * q + 1], f[4 * q + 2], f[4 * q + 3]);

    // G = s3*(W3a @ f) + b3, stored PERMUTED for pass2 fragment loads:
    // pair hp (= cols 2hp, 2hp+1) goes to ull index (hp&3)*4 + (hp>>2)
#pragma unroll
    for (int hp = 0; hp < 16; hp++) acc[hp] = pack2(sB3[2 * hp], sB3[2 * hp + 1]);
#pragma unroll
    for (int c = 0; c < HH; c++) {
        ull xd = pack2(f[c], f[c]);
#pragma unroll
        for (int hp = 0; hp < 16; hp++) acc[hp] = ffma2(sW3A[c][hp], xd, acc[hp]);
    }
    ull* Grow = (ull*)(dG + (size_t)p * HH);
#pragma unroll
    for (int hp = 0; hp < 16; hp++) Grow[(hp & 3) * 4 + (hp >> 2)] = acc[hp];

    const float* xp = xyz + (size_t)p * 3;
    dXYZ4[p] = make_float4(xp[0], xp[1], xp[2], 0.0f);
}

// ================== pass 2: warp-per-point tf32 MMA + max-pool ==================
// GEMM per point: D[16 k, 32 out] = fx[16 k, 32 c] @ B[32 c, 32 out] + G[j_k, out]
// m16n8k8 fragments: gid = lane>>2 (k-row), tig = lane&3.
__global__ void __launch_bounds__(256, 2) pass2_kernel(const unsigned int* __restrict__ idxw) {
    __shared__ float4 sCA[HH], sCB[HH];
    int tid = threadIdx.x;
    if (tid < HH) { sCA[tid] = dCoefA[tid]; sCB[tid] = dCoefB[tid]; }
    __syncthreads();
    int lane = tid & 31, warp = tid >> 5;
    int gid = lane >> 2, tig = lane & 3;
    int shift = dIdx64;

    // B fragments resident in registers: b0 = B[c=8s+tig][h=nt*8+gid], b1 = c+4
    u32 B[4][4][2];
#pragma unroll
    for (int s = 0; s < 4; s++)
#pragma unroll
        for (int nt = 0; nt < 4; nt++) {
            B[s][nt][0] = dW3Btf[(nt * 8 + gid) * HH + 8 * s + tig];
            B[s][nt][1] = dW3Btf[(nt * 8 + gid) * HH + 8 * s + tig + 4];
        }

    int pbase = (blockIdx.x * 8 + warp) * PPW;
    int bBase = (pbase / NN) * NN;

#pragma unroll 1
    for (int i = 0; i < PPW; i++) {
        int p = pbase + i;
        // neighbor indices: lanes 0..15 hold k=0..15
        unsigned jv = 0;
        if (lane < 16) jv = idxw[(size_t)((u32)p * 16u + (u32)lane) << shift];
        int j0 = bBase + (int)__shfl_sync(0xffffffffu, jv, gid);        // k = gid
        int j1 = bBase + (int)__shfl_sync(0xffffffffu, jv, gid + 8);    // k = gid+8

        float4 xc = dXYZ4[p];
        float4 xa = dXYZ4[j0];
        float4 xb = dXYZ4[j1];

        // C init = G rows (permuted layout: thread's 8 floats contiguous at tig*8)
        const float4* g0p = (const float4*)(dG + (size_t)j0 * HH + tig * 8);
        const float4* g1p = (const float4*)(dG + (size_t)j1 * HH + tig * 8);
        float4 qa0 = g0p[0], qa1 = g0p[1];
        float4 qb0 = g1p[0], qb1 = g1p[1];
        float C[4][4];
        C[0][0] = qa0.x; C[0][1] = qa0.y; C[1][0] = qa0.z; C[1][1] = qa0.w;
        C[2][0] = qa1.x; C[2][1] = qa1.y; C[3][0] = qa1.z; C[3][1] = qa1.w;
        C[0][2] = qb0.x; C[0][3] = qb0.y; C[1][2] = qb0.z; C[1][3] = qb0.w;
        C[2][2] = qb1.x; C[2][3] = qb1.y; C[3][2] = qb1.z; C[3][3] = qb1.w;

        float dxa = xc.x - xa.x, dya = xc.y - xa.y, dza = xc.z - xa.z;
        float dis0 = sqrtf(dxa * dxa + dya * dya + dza * dza);
        float dxb = xc.x - xb.x, dyb = xc.y - xb.y, dzb = xc.z - xb.z;
        float dis1 = sqrtf(dxb * dxb + dyb * dyb + dzb * dzb);

        // fx into A fragments: a0=(gid, c), a1=(gid+8, c), a2=(gid, c+4), a3=(gid+8, c+4); c=8s+tig
        u32 A[4][4];
#pragma unroll
        for (int t = 0; t < 8; t++) {
            float4 ca = sCA[tig + 4 * t];
            float4 cb = sCB[tig + 4 * t];
            float bb = fmaf(cb.x, xc.x, fmaf(cb.y, xc.y, fmaf(cb.z, xc.z, cb.w)));
            float v0 = fmaxf(fmaf(ca.x, xa.x, fmaf(ca.y, xa.y, fmaf(ca.z, xa.z, fmaf(ca.w, dis0, bb)))), 0.0f);
            float v1 = fmaxf(fmaf(ca.x, xb.x, fmaf(ca.y, xb.y, fmaf(ca.z, xb.z, fmaf(ca.w, dis1, bb)))), 0.0f);
            int s = t >> 1;
            if ((t & 1) == 0) { A[s][0] = cvt_tf32(v0); A[s][1] = cvt_tf32(v1); }
            else              { A[s][2] = cvt_tf32(v0); A[s][3] = cvt_tf32(v1); }
        }

#pragma unroll
        for (int s = 0; s < 4; s++)
#pragma unroll
            for (int nt = 0; nt < 4; nt++)
                mma_tf32(C[nt][0], C[nt][1], C[nt][2], C[nt][3],
                         A[s][0], A[s][1], A[s][2], A[s][3], B[s][nt][0], B[s][nt][1]);

        // max over 16 k-rows: fold rows gid / gid+8, then butterfly over gid bits
        float r0[4], r1[4];
#pragma unroll
        for (int nt = 0; nt < 4; nt++) {
            r0[nt] = fmaxf(C[nt][0], C[nt][2]);
            r1[nt] = fmaxf(C[nt][1], C[nt][3]);
        }
#pragma unroll
        for (int off = 4; off <= 16; off <<= 1)
#pragma unroll
            for (int nt = 0; nt < 4; nt++) {
                r0[nt] = fmaxf(r0[nt], __shfl_xor_sync(0xffffffffu, r0[nt], off));
                r1[nt] = fmaxf(r1[nt], __shfl_xor_sync(0xffffffffu, r1[nt], off));
            }
        if (gid == 0) {
#pragma unroll
            for (int nt = 0; nt < 4; nt++) {
                float2 v = make_float2(fmaxf(r0[nt], 0.0f), fmaxf(r1[nt], 0.0f));
                *(float2*)(dFC + (size_t)p * HH + nt * 8 + 2 * tig) = v;
            }
        }
    }
}

// ================== pass 3: out = relu(W4' @ [fc; f] + b4) ==================
__global__ void __launch_bounds__(64) pass3_kernel(float* __restrict__ out) {
    __shared__ ull sW4[2 * HH][DD / 2];  // 16 KB
    __shared__ float sB4[DD];
    __shared__ float sFC[64 * 33];
    __shared__ float sF[64 * 33];
    int tid = threadIdx.x;
    for (int i = tid; i < 2 * HH * (DD / 2); i += 64) ((ull*)sW4)[i] = ((ull*)dW4P)[i];
    if (tid < DD) sB4[tid] = dB4[tid];
    int pbase = blockIdx.x * 64;
    for (int i = tid; i < 64 * HH; i += 64) {
        int r = i >> 5, c = i & 31;
        sFC[r * 33 + c] = dFC[(size_t)pbase * HH + i];
        sF[r * 33 + c] = dF[(size_t)pbase * HH + i];
    }
    __syncthreads();

    int p = pbase + tid;
    int b = p / NN;
    int n = p - b * NN;

    ull acc[DD / 2];
#pragma unroll
    for (int dp = 0; dp < 32; dp++) acc[dp] = pack2(sB4[2 * dp], sB4[2 * dp + 1]);
#pragma unroll
    for (int c = 0; c < HH; c++) {
        float v = sFC[tid * 33 + c];
        ull x2 = pack2(v, v);
        const ulonglong2* wr = (const ulonglong2*)sW4[c];
#pragma unroll
        for (int dq = 0; dq < 16; dq++) {
            ulonglong2 w = wr[dq];
            acc[2 * dq] = ffma2(w.x, x2, acc[2 * dq]);
            acc[2 * dq + 1] = ffma2(w.y, x2, acc[2 * dq + 1]);
        }
    }
#pragma unroll
    for (int c = 0; c < HH; c++) {
        float v = sF[tid * 33 + c];
        ull x2 = pack2(v, v);
        const ulonglong2* wr = (const ulonglong2*)sW4[HH + c];
#pragma unroll
        for (int dq = 0; dq < 16; dq++) {
            ulonglong2 w = wr[dq];
            acc[2 * dq] = ffma2(w.x, x2, acc[2 * dq]);
            acc[2 * dq + 1] = ffma2(w.y, x2, acc[2 * dq + 1]);
        }
    }
    float* op = out + (size_t)b * DD * NN + n;
#pragma unroll
    for (int dp = 0; dp < 32; dp++) {
        float lo, hi;
        unpack2(acc[dp], lo, hi);
        op[(size_t)(2 * dp) * NN] = fmaxf(lo, 0.0f);
        op[(size_t)(2 * dp + 1) * NN] = fmaxf(hi, 0.0f);
    }
}

// ================== launch ==================
extern "C" void kernel_launch(void* const* d_in, const int* in_sizes, int n_in,
                              void* d_out, int out_size) {
    const float *feat, *xyz, *W1, *W2, *W3, *W4;
    const float *g1, *b1, *g2, *b2, *g3, *b3, *g4, *b4;
    const void* idx;
    if (n_in >= 3 && in_sizes[2] == 320) {
        feat = (const float*)d_in[0];  xyz = (const float*)d_in[1];
        W1 = (const float*)d_in[2];    g1 = (const float*)d_in[3];  b1 = (const float*)d_in[4];
        W2 = (const float*)d_in[5];    g2 = (const float*)d_in[6];  b2 = (const float*)d_in[7];
        W3 = (const float*)d_in[8];    g3 = (const float*)d_in[9];  b3 = (const float*)d_in[10];
        W4 = (const float*)d_in[11];   g4 = (const float*)d_in[12]; b4 = (const float*)d_in[13];
        idx = d_in[14];
    } else {
        feat = (const float*)d_in[0];  xyz = (const float*)d_in[1];  idx = d_in[2];
        W1 = (const float*)d_in[3];    W2 = (const float*)d_in[4];
        W3 = (const float*)d_in[5];    W4 = (const float*)d_in[6];
        g1 = (const float*)d_in[7];    b1 = (const float*)d_in[8];
        g2 = (const float*)d_in[9];    b2 = (const float*)d_in[10];
        g3 = (const float*)d_in[11];   b3 = (const float*)d_in[12];
        g4 = (const float*)d_in[13];   b4 = (const float*)d_in[14];
    }
    prep_kernel<<<1, 256>>>(W1, W2, W3, W4, g1, b1, g2, b2, g3, b3, g4, b4);
    detect_kernel<<<1, 256>>>((const unsigned int*)idx);
    pass1_kernel<<<NPTS / 128, 128>>>(feat, xyz);
    pass2_kernel<<<NPTS / (8 * PPW), 256>>>((const unsigned int*)idx);
    pass3_kernel<<<NPTS / 64, 64>>>((float*)d_out);
}

// round 13
// speedup vs baseline: 1.6387x; 1.0001x over previous
#include <cuda_runtime.h>
#include <cstdint>
#include <float.h>

#define BB 4
#define NN 40960
#define KK 16
#define DD 64
#define HH 32
#define NPTS (BB * NN)
#define EPSV 1e-5f
#define PPW 16   // points per warp in pass2

typedef unsigned long long ull;
typedef unsigned int u32;

// ---------- packed f32x2 helpers ----------
__device__ __forceinline__ ull ffma2(ull a, ull b, ull c) {
    ull d;
    asm("fma.rn.f32x2 %0, %1, %2, %3;" : "=l"(d) : "l"(a), "l"(b), "l"(c));
    return d;
}
__device__ __forceinline__ ull pack2(float lo, float hi) {
    ull d;
    asm("mov.b64 %0, {%1, %2};" : "=l"(d) : "f"(lo), "f"(hi));
    return d;
}
__device__ __forceinline__ void unpack2(ull v, float& lo, float& hi) {
    asm("mov.b64 {%0, %1}, %2;" : "=f"(lo), "=f"(hi) : "l"(v));
}
__device__ __forceinline__ u32 cvt_tf32(float f) {
    u32 r;
    asm("cvt.rna.tf32.f32 %0, %1;" : "=r"(r) : "f"(f));
    return r;
}
__device__ __forceinline__ void mma_tf32(float& c0, float& c1, float& c2, float& c3,
                                         u32 a0, u32 a1, u32 a2, u32 a3, u32 b0, u32 b1) {
    asm("mma.sync.aligned.m16n8k8.row.col.f32.tf32.tf32.f32 "
        "{%0,%1,%2,%3}, {%4,%5,%6,%7}, {%8,%9}, {%0,%1,%2,%3};"
        : "+f"(c0), "+f"(c1), "+f"(c2), "+f"(c3)
        : "r"(a0), "r"(a1), "r"(a2), "r"(a3), "r"(b0), "r"(b1));
}
__device__ __forceinline__ u32 smem_u32(const void* p) {
    return (u32)__cvta_generic_to_shared(p);
}

// ---------- folded weights ----------
__device__ ull dW2P[DD][HH / 2];        // [c][hp]  (pass1)
__device__ ull dW3AP[HH][HH / 2];       // W3[:, 0:32] (pass1)
__device__ u32 dW3Btf[HH * HH];         // [h][c] = tf32(s3*W3[h][32+c])  (pass2 B frags)
__device__ ull dW4P[2 * HH][DD / 2];    // [c][dp] (pass3)
__device__ float4 dCoefA[HH];           // (m1x, m1y, m1z, w1d) per channel
__device__ float4 dCoefB[HH];           // (m0x, m0y, m0z, b1)  per channel
__device__ float dB2[HH], dB3[HH], dB4[DD];
__device__ int dIdx64;

// ---------- scratch ----------
__device__ float dF[NPTS * HH];     // f per point (post-ReLU)
__device__ float dG[NPTS * HH];     // G = s3*(W3a@f)+b3, PERMUTED for fragment loads
__device__ float dFC[NPTS * HH];    // max-pooled f_concat (post-ReLU), plain order
__device__ float4 dXYZ4[NPTS];      // (x, y, z, 0)
__device__ int dIdx32buf[NPTS * KK];// neigh_idx narrowed to int32

// ================== prep ==================
__global__ void prep_kernel(const float* __restrict__ W1, const float* __restrict__ W2,
                            const float* __restrict__ W3, const float* __restrict__ W4,
                            const float* __restrict__ g1, const float* __restrict__ b1,
                            const float* __restrict__ g2, const float* __restrict__ b2,
                            const float* __restrict__ g3, const float* __restrict__ b3,
                            const float* __restrict__ g4, const float* __restrict__ b4) {
    int t = threadIdx.x;
    float inv = rsqrtf(1.0f + EPSV);
    for (int i = t; i < DD * (HH / 2); i += blockDim.x) {
        int c = i >> 4, hp = i & 15;
        dW2P[c][hp] = pack2(g2[2 * hp] * inv * W2[(2 * hp) * DD + c],
                            g2[2 * hp + 1] * inv * W2[(2 * hp + 1) * DD + c]);
    }
    for (int i = t; i < HH * (HH / 2); i += blockDim.x) {
        int c = i >> 4, hp = i & 15;
        float s0 = g3[2 * hp] * inv, s1 = g3[2 * hp + 1] * inv;
        dW3AP[c][hp] = pack2(s0 * W3[(2 * hp) * (2 * HH) + c],
                             s1 * W3[(2 * hp + 1) * (2 * HH) + c]);
    }
    for (int i = t; i < HH * HH; i += blockDim.x) {
        int h = i >> 5, c = i & 31;
        dW3Btf[h * HH + c] = cvt_tf32(g3[h] * inv * W3[h * (2 * HH) + HH + c]);
    }
    for (int i = t; i < (2 * HH) * (DD / 2); i += blockDim.x) {
        int c = i >> 5, dp = i & 31;
        dW4P[c][dp] = pack2(g4[2 * dp] * inv * W4[(2 * dp) * (2 * HH) + c],
                            g4[2 * dp + 1] * inv * W4[(2 * dp + 1) * (2 * HH) + c]);
    }
    for (int c = t; c < HH; c += blockDim.x) {
        float s = g1[c] * inv;
        dCoefA[c] = make_float4(s * (W1[c * 10 + 7] - W1[c * 10 + 1]),
                                s * (W1[c * 10 + 8] - W1[c * 10 + 2]),
                                s * (W1[c * 10 + 9] - W1[c * 10 + 3]),
                                s * W1[c * 10 + 0]);
        dCoefB[c] = make_float4(s * (W1[c * 10 + 1] + W1[c * 10 + 4]),
                                s * (W1[c * 10 + 2] + W1[c * 10 + 5]),
                                s * (W1[c * 10 + 3] + W1[c * 10 + 6]),
                                b1[c]);
        dB2[c] = b2[c];
        dB3[c] = b3[c];
    }
    for (int d = t; d < DD; d += blockDim.x) dB4[d] = b4[d];
}

// ================== detect int64 vs int32 neigh_idx ==================
__global__ void detect_kernel(const unsigned int* __restrict__ w) {
    __shared__ int sBad;
    if (threadIdx.x == 0) sBad = 0;
    __syncthreads();
    unsigned int acc = 0;
    for (int i = threadIdx.x; i < 2048; i += blockDim.x) acc |= w[2 * i + 1];
    if (acc) atomicOr(&sBad, 1);
    __syncthreads();
    if (threadIdx.x == 0) dIdx64 = (sBad == 0) ? 1 : 0;
}

// ================== narrow neigh_idx to int32 (coalesced for pass2) ==================
__global__ void convert_kernel(const unsigned int* __restrict__ idxw) {
    int i = blockIdx.x * 256 + threadIdx.x;
    dIdx32buf[i] = (int)idxw[(size_t)i << dIdx64];
}

// ================== pass 1: per-point f, G (permuted), xyz4 ==================
__global__ void __launch_bounds__(128) pass1_kernel(const float* __restrict__ feat,
                                                    const float* __restrict__ xyz) {
    __shared__ ull sW2[DD][HH / 2];
    __shared__ ull sW3A[HH][HH / 2];
    __shared__ float sB2[HH], sB3[HH];
    int tid = threadIdx.x;
    for (int i = tid; i < DD * (HH / 2); i += 128) ((ull*)sW2)[i] = ((ull*)dW2P)[i];
    for (int i = tid; i < HH * (HH / 2); i += 128) ((ull*)sW3A)[i] = ((ull*)dW3AP)[i];
    if (tid < HH) { sB2[tid] = dB2[tid]; sB3[tid] = dB3[tid]; }
    __syncthreads();

    int p = blockIdx.x * 128 + tid;
    int b = p / NN;
    int n = p - b * NN;

    ull acc[HH / 2];
#pragma unroll
    for (int hp = 0; hp < 16; hp++) acc[hp] = 0ull;
    const float* fp = feat + (size_t)b * DD * NN + n;
#pragma unroll
    for (int c = 0; c < DD; c++) {
        float x = fp[(size_t)c * NN];
        ull xd = pack2(x, x);
#pragma unroll
        for (int hp = 0; hp < 16; hp++) acc[hp] = ffma2(sW2[c][hp], xd, acc[hp]);
    }
    float f[HH];
#pragma unroll
    for (int hp = 0; hp < 16; hp++) {
        float lo, hi;
        unpack2(acc[hp], lo, hi);
        f[2 * hp] = fmaxf(lo + sB2[2 * hp], 0.0f);
        f[2 * hp + 1] = fmaxf(hi + sB2[2 * hp + 1], 0.0f);
    }
    float* Frow = dF + (size_t)p * HH;
#pragma unroll
    for (int q = 0; q < 8; q++)
        ((float4*)Frow)[q] = make_float4(f[4 * q], f[4 * q + 1], f[4 * q + 2], f[4 * q + 3]);

    // G = s3*(W3a @ f) + b3, stored PERMUTED for pass2 fragment loads
#pragma unroll
    for (int hp = 0; hp < 16; hp++) acc[hp] = pack2(sB3[2 * hp], sB3[2 * hp + 1]);
#pragma unroll
    for (int c = 0; c < HH; c++) {
        ull xd = pack2(f[c], f[c]);
#pragma unroll
        for (int hp = 0; hp < 16; hp++) acc[hp] = ffma2(sW3A[c][hp], xd, acc[hp]);
    }
    ull* Grow = (ull*)(dG + (size_t)p * HH);
#pragma unroll
    for (int hp = 0; hp < 16; hp++) Grow[(hp & 3) * 4 + (hp >> 2)] = acc[hp];

    const float* xp = xyz + (size_t)p * 3;
    dXYZ4[p] = make_float4(xp[0], xp[1], xp[2], 0.0f);
}

// ================== pass 2: pipelined gather + warp-per-point tf32 MMA ==================
// staged row (36 floats): [0:32] = permuted G of neighbor j, [32:36] = xyz4 of j
#define RS 36

__global__ void __launch_bounds__(256, 2) pass2_kernel() {
    __shared__ float sG[2][8][16 * RS];      // 36864 B, double-buffered stage
    __shared__ int sIdx[8][256];             // 8192 B, per-warp neighbor indices
    __shared__ float4 sCA[HH], sCB[HH];      // 1024 B
    int tid = threadIdx.x;
    if (tid < HH) { sCA[tid] = dCoefA[tid]; sCB[tid] = dCoefB[tid]; }
    {
        const int4* src = (const int4*)dIdx32buf + (size_t)blockIdx.x * 512;
        int4* dst = (int4*)sIdx;
        for (int t = tid; t < 512; t += 256) dst[t] = src[t];
    }
    __syncthreads();

    int lane = tid & 31, warp = tid >> 5;
    int gid = lane >> 2, tig = lane & 3;

    // B fragments resident in registers
    u32 B[4][4][2];
#pragma unroll
    for (int s = 0; s < 4; s++)
#pragma unroll
        for (int nt = 0; nt < 4; nt++) {
            B[s][nt][0] = dW3Btf[(nt * 8 + gid) * HH + 8 * s + tig];
            B[s][nt][1] = dW3Btf[(nt * 8 + gid) * HH + 8 * s + tig + 4];
        }

    int pbase = (blockIdx.x * 8 + warp) * PPW;
    int bBase = (pbase / NN) * NN;
    const int* iw = sIdx[warp];
    float* buf0 = sG[0][warp];
    float* buf1 = sG[1][warp];

    // ---- staging: 16 rows x 9 chunks of 16B (8 G chunks + 1 xyz chunk) ----
#define STAGE(I, BUF)                                                                  \
    {                                                                                  \
        _Pragma("unroll")                                                              \
        for (int u = 0; u < 5; u++) {                                                  \
            int c = u * 32 + lane;                                                     \
            if (c < 144) {                                                             \
                int row = c / 9;                                                       \
                int ch = c - row * 9;                                                  \
                int j = bBase + iw[(I) * 16 + row];                                    \
                const float* src = (ch < 8) ? (dG + (size_t)j * HH + ch * 4)           \
                                            : (const float*)(dXYZ4 + j);               \
                u32 dst = smem_u32((BUF) + row * RS + ch * 4);                         \
                asm volatile("cp.async.cg.shared.global [%0], [%1], 16;"               \
                             :: "r"(dst), "l"(src));                                   \
            }                                                                          \
        }                                                                              \
        asm volatile("cp.async.commit_group;");                                        \
    }

    STAGE(0, buf0);

#pragma unroll 1
    for (int i = 0; i < PPW; i++) {
        float* cbuf = (i & 1) ? buf1 : buf0;
        float* nbuf = (i & 1) ? buf0 : buf1;
        if (i < PPW - 1) {
            STAGE(i + 1, nbuf);
            asm volatile("cp.async.wait_group 1;");
        } else {
            asm volatile("cp.async.wait_group 0;");
        }
        __syncwarp();

        int p = pbase + i;
        float4 xc = dXYZ4[p];  // uniform per warp
        float4 xa = *(const float4*)(cbuf + gid * RS + 32);
        float4 xb = *(const float4*)(cbuf + (gid + 8) * RS + 32);

        // C init = staged G rows
        const float4* g0p = (const float4*)(cbuf + gid * RS + tig * 8);
        const float4* g1p = (const float4*)(cbuf + (gid + 8) * RS + tig * 8);
        float4 qa0 = g0p[0], qa1 = g0p[1];
        float4 qb0 = g1p[0], qb1 = g1p[1];
        float C[4][4];
        C[0][0] = qa0.x; C[0][1] = qa0.y; C[1][0] = qa0.z; C[1][1] = qa0.w;
        C[2][0] = qa1.x; C[2][1] = qa1.y; C[3][0] = qa1.z; C[3][1] = qa1.w;
        C[0][2] = qb0.x; C[0][3] = qb0.y; C[1][2] = qb0.z; C[1][3] = qb0.w;
        C[2][2] = qb1.x; C[2][3] = qb1.y; C[3][2] = qb1.z; C[3][3] = qb1.w;

        float dxa = xc.x - xa.x, dya = xc.y - xa.y, dza = xc.z - xa.z;
        float dis0 = sqrtf(dxa * dxa + dya * dya + dza * dza);
        float dxb = xc.x - xb.x, dyb = xc.y - xb.y, dzb = xc.z - xb.z;
        float dis1 = sqrtf(dxb * dxb + dyb * dyb + dzb * dzb);

        // fx into A fragments
        u32 A[4][4];
#pragma unroll
        for (int t = 0; t < 8; t++) {
            float4 ca = sCA[tig + 4 * t];
            float4 cb = sCB[tig + 4 * t];
            float bb = fmaf(cb.x, xc.x, fmaf(cb.y, xc.y, fmaf(cb.z, xc.z, cb.w)));
            float v0 = fmaxf(fmaf(ca.x, xa.x, fmaf(ca.y, xa.y, fmaf(ca.z, xa.z, fmaf(ca.w, dis0, bb)))), 0.0f);
            float v1 = fmaxf(fmaf(ca.x, xb.x, fmaf(ca.y, xb.y, fmaf(ca.z, xb.z, fmaf(ca.w, dis1, bb)))), 0.0f);
            int s = t >> 1;
            if ((t & 1) == 0) { A[s][0] = cvt_tf32(v0); A[s][1] = cvt_tf32(v1); }
            else              { A[s][2] = cvt_tf32(v0); A[s][3] = cvt_tf32(v1); }
        }

#pragma unroll
        for (int s = 0; s < 4; s++)
#pragma unroll
            for (int nt = 0; nt < 4; nt++)
                mma_tf32(C[nt][0], C[nt][1], C[nt][2], C[nt][3],
                         A[s][0], A[s][1], A[s][2], A[s][3], B[s][nt][0], B[s][nt][1]);

        // max over 16 k-rows
        float r0[4], r1[4];
#pragma unroll
        for (int nt = 0; nt < 4; nt++) {
            r0[nt] = fmaxf(C[nt][0], C[nt][2]);
            r1[nt] = fmaxf(C[nt][1], C[nt][3]);
        }
#pragma unroll
        for (int off = 4; off <= 16; off <<= 1)
#pragma unroll
            for (int nt = 0; nt < 4; nt++) {
                r0[nt] = fmaxf(r0[nt], __shfl_xor_sync(0xffffffffu, r0[nt], off));
                r1[nt] = fmaxf(r1[nt], __shfl_xor_sync(0xffffffffu, r1[nt], off));
            }
        if (gid == 0) {
#pragma unroll
            for (int nt = 0; nt < 4; nt++) {
                float2 v = make_float2(fmaxf(r0[nt], 0.0f), fmaxf(r1[nt], 0.0f));
                *(float2*)(dFC + (size_t)p * HH + nt * 8 + 2 * tig) = v;
            }
        }
    }
#undef STAGE
}

// ================== pass 3: out = relu(W4' @ [fc; f] + b4) ==================
__global__ void __launch_bounds__(64) pass3_kernel(float* __restrict__ out) {
    __shared__ ull sW4[2 * HH][DD / 2];  // 16 KB
    __shared__ float sB4[DD];
    __shared__ float sFC[64 * 33];
    __shared__ float sF[64 * 33];
    int tid = threadIdx.x;
    for (int i = tid; i < 2 * HH * (DD / 2); i += 64) ((ull*)sW4)[i] = ((ull*)dW4P)[i];
    if (tid < DD) sB4[tid] = dB4[tid];
    int pbase = blockIdx.x * 64;
    for (int i = tid; i < 64 * HH; i += 64) {
        int r = i >> 5, c = i & 31;
        sFC[r * 33 + c] = dFC[(size_t)pbase * HH + i];
        sF[r * 33 + c] = dF[(size_t)pbase * HH + i];
    }
    __syncthreads();

    int p = pbase + tid;
    int b = p / NN;
    int n = p - b * NN;

    ull acc[DD / 2];
#pragma unroll
    for (int dp = 0; dp < 32; dp++) acc[dp] = pack2(sB4[2 * dp], sB4[2 * dp + 1]);
#pragma unroll
    for (int c = 0; c < HH; c++) {
        float v = sFC[tid * 33 + c];
        ull x2 = pack2(v, v);
        const ulonglong2* wr = (const ulonglong2*)sW4[c];
#pragma unroll
        for (int dq = 0; dq < 16; dq++) {
            ulonglong2 w = wr[dq];
            acc[2 * dq] = ffma2(w.x, x2, acc[2 * dq]);
            acc[2 * dq + 1] = ffma2(w.y, x2, acc[2 * dq + 1]);
        }
    }
#pragma unroll
    for (int c = 0; c < HH; c++) {
        float v = sF[tid * 33 + c];
        ull x2 = pack2(v, v);
        const ulonglong2* wr = (const ulonglong2*)sW4[HH + c];
#pragma unroll
        for (int dq = 0; dq < 16; dq++) {
            ulonglong2 w = wr[dq];
            acc[2 * dq] = ffma2(w.x, x2, acc[2 * dq]);
            acc[2 * dq + 1] = ffma2(w.y, x2, acc[2 * dq + 1]);
        }
    }
    float* op = out + (size_t)b * DD * NN + n;
#pragma unroll
    for (int dp = 0; dp < 32; dp++) {
        float lo, hi;
        unpack2(acc[dp], lo, hi);
        op[(size_t)(2 * dp) * NN] = fmaxf(lo, 0.0f);
        op[(size_t)(2 * dp + 1) * NN] = fmaxf(hi, 0.0f);
    }
}

// ================== launch ==================
extern "C" void kernel_launch(void* const* d_in, const int* in_sizes, int n_in,
                              void* d_out, int out_size) {
    const float *feat, *xyz, *W1, *W2, *W3, *W4;
    const float *g1, *b1, *g2, *b2, *g3, *b3, *g4, *b4;
    const void* idx;
    if (n_in >= 3 && in_sizes[2] == 320) {
        feat = (const float*)d_in[0];  xyz = (const float*)d_in[1];
        W1 = (const float*)d_in[2];    g1 = (const float*)d_in[3];  b1 = (const float*)d_in[4];
        W2 = (const float*)d_in[5];    g2 = (const float*)d_in[6];  b2 = (const float*)d_in[7];
        W3 = (const float*)d_in[8];    g3 = (const float*)d_in[9];  b3 = (const float*)d_in[10];
        W4 = (const float*)d_in[11];   g4 = (const float*)d_in[12]; b4 = (const float*)d_in[13];
        idx = d_in[14];
    } else {
        feat = (const float*)d_in[0];  xyz = (const float*)d_in[1];  idx = d_in[2];
        W1 = (const float*)d_in[3];    W2 = (const float*)d_in[4];
        W3 = (const float*)d_in[5];    W4 = (const float*)d_in[6];
        g1 = (const float*)d_in[7];    b1 = (const float*)d_in[8];
        g2 = (const float*)d_in[9];    b2 = (const float*)d_in[10];
        g3 = (const float*)d_in[11];   b3 = (const float*)d_in[12];
        g4 = (const float*)d_in[13];   b4 = (const float*)d_in[14];
    }
    prep_kernel<<<1, 256>>>(W1, W2, W3, W4, g1, b1, g2, b2, g3, b3, g4, b4);
    detect_kernel<<<1, 256>>>((const unsigned int*)idx);
    convert_kernel<<<NPTS * KK / 256, 256>>>((const unsigned int*)idx);
    pass1_kernel<<<NPTS / 128, 128>>>(feat, xyz);
    pass2_kernel<<<NPTS / (8 * PPW), 256>>>();
    pass3_kernel<<<NPTS / 64, 64>>>((float*)d_out);
}